// round 15
// baseline (speedup 1.0000x reference)
#include <cuda_runtime.h>
#include <cuda_bf16.h>
#include <math.h>

// -------- scratch (static device globals; no allocation anywhere) ----------
#define CAND_CAP   (1 << 20)
#define SMEM_KEYS  2048
#define NSAMP      256
#define NBLOCKS    592                 // 148 SMs x 4 blocks -> exactly 1 wave
#define NTHREADS   256
__device__ float2 g_cand[CAND_CAP];    // .x = d2, .y = __int_as_float(index)
__device__ int    g_count;             // reset at end of each run
__device__ int    g_pub;
__device__ int    g_done;
__device__ int    g_flag;
__device__ float  g_thresh;            // d2 threshold (<= true 16th-largest d2)
__device__ float  g_bmax[NSAMP];

#define APPEND(D2, J) do { \
    if ((D2) >= thr) { \
        const int pos = atomicAdd(&g_count, 1); \
        if (pos < CAND_CAP) g_cand[pos] = make_float2((D2), __int_as_float(J)); \
    } } while (0)

// ---------------------------------------------------------------------------
// ONE persistent kernel, single wave. 8 points/thread via 12 NAMED float4
// registers -> 24 KB in flight per SM (32 warps x 768 B), covering the
// ~17 KB latency-bandwidth product that capped R13/R14 at ~4.1 TB/s.
//
// Threshold: 16th largest of nsamp maxima over DISJOINT 2048-pt chunks =>
// >= 16 distinct points >= thr => thr <= global 16th-largest d^2.
// Deadlock-free: single wave, samplers publish before anyone spins.
// ---------------------------------------------------------------------------
__global__ void __launch_bounds__(NTHREADS, 4)
k_locse(const float* __restrict__ P,
        const float* __restrict__ W,    // (3,10) row-major
        const float* __restrict__ bb,   // (3,)
        const int*   __restrict__ ip,
        float* __restrict__ out,        // (16,6)
        int N, int nblocks, int nsamp)
{
    __shared__ float swarpf[8];
    __shared__ float sv[256];
    __shared__ float s_thr;
    __shared__ int   s_pred;
    __shared__ int   s_bits;
    __shared__ unsigned long long keys[SMEM_KEYS];  // 16 KB
    __shared__ unsigned long long swarp[8];
    __shared__ unsigned long long s_win;
    __shared__ int   sel[16];

    const int t = threadIdx.x;
    const int b = blockIdx.x;
    const int ngroups = N >> 3;                    // groups of 8 points
    const int gstride = nblocks * NTHREADS;

    const int i = *ip;
    const float px = P[6 * i + 0];
    const float py = P[6 * i + 1];
    const float pz = P[6 * i + 2];

    const float4* __restrict__ Pv = (const float4*)P;

    // ---- phase 1: first group, 12 named float4 loads, d2 kept in regs ----
    const int grp0 = b * NTHREADS + t;
    float d2a = -1.f, d2b = -1.f, d2c = -1.f, d2d = -1.f;
    float d2e = -1.f, d2f = -1.f, d2g = -1.f, d2h = -1.f;
    if (grp0 < ngroups) {
        const float4* s = Pv + 12ll * grp0;
        const float4 f0 = s[0],  f1 = s[1],  f2 = s[2];
        const float4 f3 = s[3],  f4 = s[4],  f5 = s[5];
        const float4 f6 = s[6],  f7 = s[7],  f8 = s[8];
        const float4 f9 = s[9],  f10 = s[10], f11 = s[11];
        { const float dx = f0.x - px, dy = f0.y - py, dz = f0.z - pz; d2a = dx*dx + dy*dy + dz*dz; }
        { const float dx = f1.z - px, dy = f1.w - py, dz = f2.x - pz; d2b = dx*dx + dy*dy + dz*dz; }
        { const float dx = f3.x - px, dy = f3.y - py, dz = f3.z - pz; d2c = dx*dx + dy*dy + dz*dz; }
        { const float dx = f4.z - px, dy = f4.w - py, dz = f5.x - pz; d2d = dx*dx + dy*dy + dz*dz; }
        { const float dx = f6.x - px, dy = f6.y - py, dz = f6.z - pz; d2e = dx*dx + dy*dy + dz*dz; }
        { const float dx = f7.z - px, dy = f7.w - py, dz = f8.x - pz; d2f = dx*dx + dy*dy + dz*dz; }
        { const float dx = f9.x - px, dy = f9.y - py, dz = f9.z - pz; d2g = dx*dx + dy*dy + dz*dz; }
        { const float dx = f10.z - px, dy = f10.w - py, dz = f11.x - pz; d2h = dx*dx + dy*dy + dz*dz; }
    }

    // ---- phase 2: samplers publish first-chunk max; last one sets thr ----
    if (b < nsamp) {
        float m = fmaxf(fmaxf(fmaxf(d2a, d2b), fmaxf(d2c, d2d)),
                        fmaxf(fmaxf(d2e, d2f), fmaxf(d2g, d2h)));
        #pragma unroll
        for (int s = 16; s > 0; s >>= 1)
            m = fmaxf(m, __shfl_xor_sync(0xffffffffu, m, s));
        if ((t & 31) == 0) swarpf[t >> 5] = m;
        __syncthreads();
        if (t == 0) {
            float mm = swarpf[0];
            #pragma unroll
            for (int w = 1; w < 8; w++) mm = fmaxf(mm, swarpf[w]);
            g_bmax[b] = mm;
            __threadfence();
            s_pred = (atomicAdd(&g_pub, 1) == nsamp - 1);
            s_bits = 0;
        }
        __syncthreads();
        if (s_pred) {
            sv[t] = (t < nsamp) ? g_bmax[t] : -1.0f;
            __syncthreads();
            const float my = sv[t];
            int g = 0;
            #pragma unroll 16
            for (int q = 0; q < 256; q++) g += (sv[q] > my) ? 1 : 0;
            if (g >= 15 && my >= 0.0f) atomicMax(&s_bits, __float_as_int(my));
            __syncthreads();
            if (t == 0) {
                g_thresh = __int_as_float(s_bits);
                __threadfence();
                atomicExch(&g_flag, 1);
            }
        }
    }

    // ---- phase 3: wait for threshold ----
    if (t == 0) {
        while (atomicAdd(&g_flag, 0) == 0) __nanosleep(64);
        __threadfence();
        s_thr = g_thresh;
    }
    __syncthreads();
    const float thr = s_thr;

    // ---- phase 4a: append survivors of the first (already-loaded) group ----
    if (grp0 < ngroups) {
        const int j0 = 8 * grp0;
        APPEND(d2a, j0 + 0); APPEND(d2b, j0 + 1);
        APPEND(d2c, j0 + 2); APPEND(d2d, j0 + 3);
        APPEND(d2e, j0 + 4); APPEND(d2f, j0 + 5);
        APPEND(d2g, j0 + 6); APPEND(d2h, j0 + 7);
    }

    // ---- phase 4b: grid-stride over remaining groups (8 pts / iter) ----
    for (int grp = grp0 + gstride; grp < ngroups; grp += gstride) {
        const float4* s = Pv + 12ll * grp;
        const float4 f0 = s[0],  f1 = s[1],  f2 = s[2];
        const float4 f3 = s[3],  f4 = s[4],  f5 = s[5];
        const float4 f6 = s[6],  f7 = s[7],  f8 = s[8];
        const float4 f9 = s[9],  f10 = s[10], f11 = s[11];
        float e0, e1, e2, e3, e4, e5, e6, e7;
        { const float dx = f0.x - px, dy = f0.y - py, dz = f0.z - pz; e0 = dx*dx + dy*dy + dz*dz; }
        { const float dx = f1.z - px, dy = f1.w - py, dz = f2.x - pz; e1 = dx*dx + dy*dy + dz*dz; }
        { const float dx = f3.x - px, dy = f3.y - py, dz = f3.z - pz; e2 = dx*dx + dy*dy + dz*dz; }
        { const float dx = f4.z - px, dy = f4.w - py, dz = f5.x - pz; e3 = dx*dx + dy*dy + dz*dz; }
        { const float dx = f6.x - px, dy = f6.y - py, dz = f6.z - pz; e4 = dx*dx + dy*dy + dz*dz; }
        { const float dx = f7.z - px, dy = f7.w - py, dz = f8.x - pz; e5 = dx*dx + dy*dy + dz*dz; }
        { const float dx = f9.x - px, dy = f9.y - py, dz = f9.z - pz; e6 = dx*dx + dy*dy + dz*dz; }
        { const float dx = f10.z - px, dy = f10.w - py, dz = f11.x - pz; e7 = dx*dx + dy*dy + dz*dz; }
        const int j0 = 8 * grp;
        APPEND(e0, j0 + 0); APPEND(e1, j0 + 1);
        APPEND(e2, j0 + 2); APPEND(e3, j0 + 3);
        APPEND(e4, j0 + 4); APPEND(e5, j0 + 5);
        APPEND(e6, j0 + 6); APPEND(e7, j0 + 7);
    }

    // ---- phase 4c: scalar tail (N not divisible by 8), block 0 ----
    if (b == 0 && t < (N & 7)) {
        const int j = (ngroups << 3) + t;
        const float dx = P[6 * j + 0] - px;
        const float dy = P[6 * j + 1] - py;
        const float dz = P[6 * j + 2] - pz;
        const float d2 = dx * dx + dy * dy + dz * dz;
        APPEND(d2, j);
    }

    // ---- phase 5: last block does exact top-16 + epilogue ----
    __threadfence();
    __syncthreads();
    if (t == 0) s_pred = (atomicAdd(&g_done, 1) == nblocks - 1);
    __syncthreads();
    if (!s_pred) return;

    __threadfence();                      // acquire all g_cand / g_count
    int cnt = g_count;
    if (cnt > SMEM_KEYS) cnt = SMEM_KEYS; // survivors ~500; 4x margin

    // packed key: (bits(sqrt(d2)) << 32) | ~idx -> max == (d desc, idx asc),
    // matching jax.lax.top_k tie semantics.
    for (int q = t; q < cnt; q += NTHREADS) {
        const float2 cv = g_cand[q];
        const unsigned int db = __float_as_uint(sqrtf(cv.x));
        const unsigned int ik = ~(unsigned int)__float_as_int(cv.y);
        keys[q] = ((unsigned long long)db << 32) | ik;
    }
    __syncthreads();

    for (int r = 0; r < 16; r++) {
        unsigned long long mk = 0; int mpos = -1;
        for (int q = t; q < cnt; q += NTHREADS) {
            const unsigned long long kk = keys[q];
            if (kk > mk) { mk = kk; mpos = q; }
        }
        unsigned long long wk = mk;
        #pragma unroll
        for (int s = 16; s > 0; s >>= 1) {
            const unsigned long long o = __shfl_xor_sync(0xffffffffu, wk, s);
            if (o > wk) wk = o;
        }
        if ((t & 31) == 0) swarp[t >> 5] = wk;
        __syncthreads();
        if (t < 8) {
            unsigned long long v = swarp[t];
            #pragma unroll
            for (int s = 4; s > 0; s >>= 1) {
                const unsigned long long o = __shfl_xor_sync(0xffu, v, s);
                if (o > v) v = o;
            }
            if (t == 0) s_win = v;
        }
        __syncthreads();
        const unsigned long long win = s_win;
        if (mk == win && mpos >= 0) keys[mpos] = 0ULL;  // unique owner removes
        if (t == 0) sel[r] = (int)(~(unsigned int)(win & 0xFFFFFFFFULL));
        __syncthreads();
    }

    if (t < 16) {
        const int idx = sel[t];
        const float nx = P[6 * idx + 0];
        const float ny = P[6 * idx + 1];
        const float nz = P[6 * idx + 2];
        const float dx = px - nx, dy = py - ny, dz = pz - nz;
        const float dist = sqrtf(dx * dx + dy * dy + dz * dz);

        float feat[10] = {px, py, pz, nx, ny, nz, dx, dy, dz, dist};

        out[6 * t + 0] = nx;
        out[6 * t + 1] = ny;
        out[6 * t + 2] = nz;
        #pragma unroll
        for (int c = 0; c < 3; c++) {
            float acc = bb[c];
            #pragma unroll
            for (int j = 0; j < 10; j++)
                acc += feat[j] * W[c * 10 + j];
            out[6 * t + 3 + c] = acc;
        }
    }

    if (t == 0) {                       // reset for next graph replay
        g_count = 0;
        g_pub = 0;
        g_done = 0;
        atomicExch(&g_flag, 0);
    }
}

// ---------------------------------------------------------------------------
extern "C" void kernel_launch(void* const* d_in, const int* in_sizes, int n_in,
                              void* d_out, int out_size)
{
    const float* P  = (const float*)d_in[0];
    const float* W  = (const float*)d_in[1];
    const float* b  = (const float*)d_in[2];
    const int*   ip = (const int*)d_in[3];
    float* out = (float*)d_out;

    const int N = in_sizes[0] / 6;

    const int ngroups = N / 8;
    int nblocks = NBLOCKS;
    const int maxblocks = (ngroups + NTHREADS - 1) / NTHREADS;
    if (nblocks > maxblocks) nblocks = (maxblocks > 0) ? maxblocks : 1;

    int nsamp = NSAMP;
    const int fullchunks = N / (NTHREADS * 8);
    if (nsamp > fullchunks) nsamp = (fullchunks > 0) ? fullchunks : 1;
    if (nsamp > nblocks) nsamp = nblocks;

    k_locse<<<nblocks, NTHREADS>>>(P, W, b, ip, out, N, nblocks, nsamp);
}